// round 16
// baseline (speedup 1.0000x reference)
#include <cuda_runtime.h>
#include <cuda_bf16.h>
#include <cstdint>

// ---------------------------------------------------------------------------
// TimeAwareRNN  (L=256, B=512, K_IN=15, K_STATE=512, K_OUT=8, MEANDT=1)
//
// R10 measured: dur_us=40857, rel_err=4.35e-7 (fp32 everywhere, tensor=0%).
// R12-R16: 3xTF32-split mma.sync for BOTH non-recurrent GEMMs (Lx + head).
//   Split (Ah*Bh + Al*Bh + Ah*Bl) keeps ~fp32 accuracy; single-tf32's
//   persistent-bias tail risk vs rel_err<1e-3 is not worth a scarce slot.
// Scan (27ms) untouched; its port (likely bf16x2-split weights, smem-size
// neutral) is gated on this round's measured mma throughput + rel_err.
// ---------------------------------------------------------------------------

#define LSEQ   256
#define BDIM   512
#define KS     512
#define KIN    15
#define KOUT   8
#define NWX    1536
#define LB     (LSEQ * BDIM)          // 131072
#define NB     128                    // scan grid (<= 148 SMs, 1 block/SM)

// ------------------------------- scratch -----------------------------------
__device__ float g_xe[(size_t)LB * KS];        // 268 MB (reused as T)
__device__ float g_Lx[(size_t)LB * NWX];       // 805 MB
__device__ float g_states[(size_t)LB * KS];    // 268 MB
__device__ float g_hsbuf[2][BDIM * KS];        // ping-pong stage states
__device__ float g_rh[BDIM * KS];              // r*hs exchange buffer
__device__ unsigned g_barcnt = 0;              // monotonic barrier counter

// ------------------------------- helpers -----------------------------------
__device__ __forceinline__ float sigmoidf_(float x) {
    return __fdividef(1.0f, 1.0f + __expf(-x));
}

__device__ __forceinline__ uint32_t f2tf32(float x) {
    uint32_t r;
    asm("cvt.rna.tf32.f32 %0, %1;" : "=r"(r) : "f"(x));
    return r;
}

#define MMA_TF32(c, a, b) \
    asm volatile("mma.sync.aligned.m16n8k8.row.col.f32.tf32.tf32.f32 " \
        "{%0,%1,%2,%3}, {%4,%5,%6,%7}, {%8,%9}, {%0,%1,%2,%3};" \
        : "+f"((c)[0]), "+f"((c)[1]), "+f"((c)[2]), "+f"((c)[3]) \
        : "r"((a)[0]), "r"((a)[1]), "r"((a)[2]), "r"((a)[3]), \
          "r"((b)[0]), "r"((b)[1]))

// Replay-safe monotonic grid barrier (see R6 notes: every thread fences).
__device__ __forceinline__ void grid_barrier() {
    __threadfence();
    __syncthreads();
    if (threadIdx.x == 0) {
        unsigned my = atomicAdd(&g_barcnt, 1u);
        unsigned target = my - (my % NB) + NB;
        while ((int)(*(volatile unsigned*)&g_barcnt - target) < 0)
            __nanosleep(32);
        __threadfence();
    }
    __syncthreads();
}

// --------------------------- init hs = state0 ------------------------------
__global__ void init_kernel(const float* __restrict__ state0) {
    int idx = blockIdx.x * blockDim.x + threadIdx.x;
    g_hsbuf[0][idx] = state0[idx & (KS - 1)];
}

// ------------------------- y0 = Ly(h0) -> out[0] ---------------------------
__global__ void y0_kernel(const float* __restrict__ state0,
                          const float* __restrict__ Ly1,
                          const float* __restrict__ Ly2,
                          float* __restrict__ out) {
    __shared__ float t0[KS];
    __shared__ float y0s[KOUT];
    int tid = threadIdx.x;
    int lane = tid & 31, w = tid >> 5;
    for (int jj = 0; jj < 32; ++jj) {
        int j = w * 32 + jj;
        float s = 0.f;
        #pragma unroll 4
        for (int c = 0; c < 16; ++c)
            s += state0[lane * 16 + c] * Ly1[j * KS + lane * 16 + c];
        #pragma unroll
        for (int sh = 16; sh; sh >>= 1) s += __shfl_xor_sync(0xffffffffu, s, sh);
        if (lane == 0) t0[j] = tanhf(s);
    }
    __syncthreads();
    if (w < KOUT) {
        float s = 0.f;
        #pragma unroll 4
        for (int c = 0; c < 16; ++c)
            s += t0[lane * 16 + c] * Ly2[w * KS + lane * 16 + c];
        #pragma unroll
        for (int sh = 16; sh; sh >>= 1) s += __shfl_xor_sync(0xffffffffu, s, sh);
        if (lane == 0) y0s[w] = s;
    }
    __syncthreads();
    for (int u = tid; u < BDIM * KOUT; u += blockDim.x)
        out[u] = y0s[u & (KOUT - 1)];
}

// ------------------------ xe = tanh(x @ Win^T + bin) -----------------------
__global__ __launch_bounds__(256)
void xe_kernel(const float* __restrict__ seq,
               const float* __restrict__ Win,
               const float* __restrict__ bin) {
    __shared__ float sW[KS * KIN];
    __shared__ float sb[KS];
    __shared__ float sx[4][16];
    int tid = threadIdx.x;
    for (int u = tid; u < KS * KIN; u += 256) sW[u] = Win[u];
    for (int u = tid; u < KS; u += 256) sb[u] = bin[u];
    int r0 = blockIdx.x * 4;
    if (tid < 64) sx[tid >> 4][tid & 15] = seq[(size_t)(r0 + (tid >> 4)) * 16 + (tid & 15)];
    __syncthreads();
    #pragma unroll
    for (int r = 0; r < 4; ++r) {
        #pragma unroll
        for (int jj = 0; jj < 2; ++jj) {
            int j = jj * 256 + tid;
            float s = sb[j];
            #pragma unroll
            for (int k = 0; k < KIN; ++k) s = fmaf(sx[r][k], sW[j * KIN + k], s);
            g_xe[(size_t)(r0 + r) * KS + j] = tanhf(s);
        }
    }
}

// ------------- tf32 tensor-core NT GEMM: C = A @ B^T (opt tanh) ------------
// BM=BN=128, BK=16, 256 threads (8 warps), warp tile m64 x n32 via
// mma.sync.m16n8k8.tf32.  SPLIT=true -> 3xTF32 (Ah*Bh + Al*Bh + Ah*Bl) for
// near-fp32 accuracy.  M%128==0, N%128==0, K%16==0.
// Fragment layouts (PTX ISA m16n8k8 tf32): gr=lane>>2, gc=lane&3;
//   A: a0=(gr,gc) a1=(gr+8,gc) a2=(gr,gc+4) a3=(gr+8,gc+4)
//   B: b0=(k=gc,n=gr) b1=(k=gc+4,n=gr)
//   C: c0=(gr,2gc) c1=(gr,2gc+1) c2=(gr+8,2gc) c3=(gr+8,2gc+1)
template<bool TANH, bool SPLIT>
__global__ __launch_bounds__(256)
void sgemm_tc(const float* __restrict__ A, const float* __restrict__ Bm,
              float* __restrict__ C, int M, int N, int K) {
    constexpr int NS = SPLIT ? 2 : 1;
    __shared__ float As[NS][16][132];
    __shared__ float Bs[NS][16][132];
    const int tid  = threadIdx.x;
    const int lane = tid & 31;
    const int w    = tid >> 5;            // 0..7
    const int wm   = (w & 1) * 64;
    const int wn   = (w >> 1) * 32;
    const int gr   = lane >> 2;           // 0..7
    const int gc   = lane & 3;            // 0..3
    const int bn0  = blockIdx.x * 128;
    const int bm0  = blockIdx.y * 128;
    const int lm   = tid >> 2;            // 0..63
    const int lk   = (tid & 3) * 4;       // 0,4,8,12

    float c[4][4][4];
    #pragma unroll
    for (int mi = 0; mi < 4; ++mi)
        #pragma unroll
        for (int ni = 0; ni < 4; ++ni)
            #pragma unroll
            for (int q = 0; q < 4; ++q) c[mi][ni][q] = 0.f;

    const float* Ap  = A  + (size_t)(bm0 + lm) * K + lk;
    const float* Ap2 = Ap + (size_t)64 * K;
    const float* Bp  = Bm + (size_t)(bn0 + lm) * K + lk;
    const float* Bp2 = Bp + (size_t)64 * K;

    for (int k0 = 0; k0 < K; k0 += 16) {
        float4 av0 = *(const float4*)(Ap  + k0);
        float4 av1 = *(const float4*)(Ap2 + k0);
        float4 bv0 = *(const float4*)(Bp  + k0);
        float4 bv1 = *(const float4*)(Bp2 + k0);

        #define PUT(Sm, kk, mm, v) do {                                     \
            float h_ = __uint_as_float(f2tf32(v));                          \
            Sm[0][kk][mm] = h_;                                             \
            if (SPLIT) Sm[1][kk][mm] = __uint_as_float(f2tf32((v) - h_));   \
        } while (0)

        PUT(As, lk + 0, lm,      av0.x); PUT(As, lk + 1, lm,      av0.y);
        PUT(As, lk + 2, lm,      av0.z); PUT(As, lk + 3, lm,      av0.w);
        PUT(As, lk + 0, lm + 64, av1.x); PUT(As, lk + 1, lm + 64, av1.y);
        PUT(As, lk + 2, lm + 64, av1.z); PUT(As, lk + 3, lm + 64, av1.w);
        PUT(Bs, lk + 0, lm,      bv0.x); PUT(Bs, lk + 1, lm,      bv0.y);
        PUT(Bs, lk + 2, lm,      bv0.z); PUT(Bs, lk + 3, lm,      bv0.w);
        PUT(Bs, lk + 0, lm + 64, bv1.x); PUT(Bs, lk + 1, lm + 64, bv1.y);
        PUT(Bs, lk + 2, lm + 64, bv1.z); PUT(Bs, lk + 3, lm + 64, bv1.w);
        #undef PUT
        __syncthreads();

        #pragma unroll
        for (int ks = 0; ks < 16; ks += 8) {
            uint32_t af[NS][4][4];
            uint32_t bf[NS][4][2];
            #pragma unroll
            for (int s = 0; s < NS; ++s) {
                #pragma unroll
                for (int mi = 0; mi < 4; ++mi) {
                    int m0 = wm + mi * 16;
                    af[s][mi][0] = __float_as_uint(As[s][ks + gc][m0 + gr]);
                    af[s][mi][1] = __float_as_uint(As[s][ks + gc][m0 + gr + 8]);
                    af[s][mi][2] = __float_as_uint(As[s][ks + gc + 4][m0 + gr]);
                    af[s][mi][3] = __float_as_uint(As[s][ks + gc + 4][m0 + gr + 8]);
                }
                #pragma unroll
                for (int ni = 0; ni < 4; ++ni) {
                    int n0 = wn + ni * 8;
                    bf[s][ni][0] = __float_as_uint(Bs[s][ks + gc][n0 + gr]);
                    bf[s][ni][1] = __float_as_uint(Bs[s][ks + gc + 4][n0 + gr]);
                }
            }
            #pragma unroll
            for (int mi = 0; mi < 4; ++mi)
                #pragma unroll
                for (int ni = 0; ni < 4; ++ni) {
                    if (SPLIT) {
                        MMA_TF32(c[mi][ni], af[1][mi], bf[0][ni]);
                        MMA_TF32(c[mi][ni], af[0][mi], bf[1][ni]);
                    }
                    MMA_TF32(c[mi][ni], af[0][mi], bf[0][ni]);
                }
        }
        __syncthreads();
    }

    #pragma unroll
    for (int mi = 0; mi < 4; ++mi) {
        #pragma unroll
        for (int ni = 0; ni < 4; ++ni) {
            int row0 = bm0 + wm + mi * 16 + gr;
            int col  = bn0 + wn + ni * 8 + 2 * gc;
            float v0 = c[mi][ni][0], v1 = c[mi][ni][1];
            float v2 = c[mi][ni][2], v3 = c[mi][ni][3];
            if (TANH) {
                v0 = tanhf(v0); v1 = tanhf(v1);
                v2 = tanhf(v2); v3 = tanhf(v3);
            }
            *(float2*)&C[(size_t)row0 * N + col]       = make_float2(v0, v1);
            *(float2*)&C[(size_t)(row0 + 8) * N + col] = make_float2(v2, v3);
        }
    }
}

// ----------------------- persistent RK4 scan kernel ------------------------
// Unchanged from R10 PASS (dur contribution ~27ms; port decision follows the
// measured sgemm_tc throughput + rel_err).
__global__ __launch_bounds__(256, 1)
void scan_kernel(const float* __restrict__ seq,
                 const float* __restrict__ Wg,
                 const float* __restrict__ Wlin,
                 const float* __restrict__ bg,
                 const float* __restrict__ blin,
                 const float* __restrict__ state0) {
    extern __shared__ float smf[];
    float* sWz = smf;                  // [512][32]
    float* sWr = smf + KS * 32;        // [512][32]
    float* sWl = smf + 2 * KS * 32;    // [512][32]
    float* Asb = smf + 3 * KS * 32;    // [2][16*68] double-buffered A tile

    const int tid = threadIdx.x;
    const int tn  = tid & 31;
    const int tm  = tid >> 5;
    const int bm0 = (blockIdx.x & 7) * 64;
    const int j0  = (blockIdx.x >> 3) * 32;
    const int lm  = tid >> 2;
    const int lk4 = (tid & 3) * 4;

    for (int u = tid; u < 32 * 128; u += 256) {
        int jj = u >> 7;
        int kq = (u & 127) * 4;
        float4 v0 = *(const float4*)&Wg[(size_t)(j0 + jj) * KS + kq];
        float4 v1 = *(const float4*)&Wg[(size_t)(512 + j0 + jj) * KS + kq];
        float4 v2 = *(const float4*)&Wlin[(size_t)(j0 + jj) * KS + kq];
        sWz[(kq + 0) * 32 + jj] = v0.x; sWz[(kq + 1) * 32 + jj] = v0.y;
        sWz[(kq + 2) * 32 + jj] = v0.z; sWz[(kq + 3) * 32 + jj] = v0.w;
        sWr[(kq + 0) * 32 + jj] = v1.x; sWr[(kq + 1) * 32 + jj] = v1.y;
        sWr[(kq + 2) * 32 + jj] = v1.z; sWr[(kq + 3) * 32 + jj] = v1.w;
        sWl[(kq + 0) * 32 + jj] = v2.x; sWl[(kq + 1) * 32 + jj] = v2.y;
        sWl[(kq + 2) * 32 + jj] = v2.z; sWl[(kq + 3) * 32 + jj] = v2.w;
    }

    const int j = j0 + tn;
    const float bgz = bg[j];
    const float bgr = bg[512 + j];
    const float blv = blin[j];

    float hsv[8], hbv[8], kacc[8], zg[8];
    {
        float s0v = state0[j];
        #pragma unroll
        for (int i = 0; i < 8; ++i) { hsv[i] = s0v; hbv[i] = s0v; }
    }
    __syncthreads();

    int rp = 0;
    for (int t = 0; t < LSEQ; ++t) {
        float dtv[8], lz[8], lr[8], ll[8];
        #pragma unroll
        for (int i = 0; i < 8; ++i) {
            int b = bm0 + tm * 8 + i;
            dtv[i] = (t == 0) ? 0.f : seq[((size_t)(t - 1) * BDIM + b) * 16 + 15];
            size_t ro = ((size_t)t * BDIM + b) * NWX;
            lz[i] = g_Lx[ro + j];
            lr[i] = g_Lx[ro + 512 + j];
            ll[i] = g_Lx[ro + 1024 + j];
        }

        for (int st = 0; st < 4; ++st) {
            const float* hs = g_hsbuf[rp];

            float az[8], aq[8];
            #pragma unroll
            for (int i = 0; i < 8; ++i) { az[i] = 0.f; aq[i] = 0.f; }
            {
                float4 av = __ldcg((const float4*)&hs[(size_t)(bm0 + lm) * KS + lk4]);
                Asb[(lk4 + 0) * 68 + lm] = av.x; Asb[(lk4 + 1) * 68 + lm] = av.y;
                Asb[(lk4 + 2) * 68 + lm] = av.z; Asb[(lk4 + 3) * 68 + lm] = av.w;
                for (int k0 = 0; k0 < KS; k0 += 16) {
                    __syncthreads();
                    float4 nv;
                    const bool more = (k0 + 16 < KS);
                    if (more)
                        nv = __ldcg((const float4*)&hs[(size_t)(bm0 + lm) * KS + k0 + 16 + lk4]);
                    const float* Ac = Asb + ((k0 >> 4) & 1) * (16 * 68);
                    #pragma unroll
                    for (int k = 0; k < 16; ++k) {
                        float a[8];
                        *(float4*)(a)     = *(const float4*)(Ac + k * 68 + tm * 8);
                        *(float4*)(a + 4) = *(const float4*)(Ac + k * 68 + tm * 8 + 4);
                        float bz = sWz[(k0 + k) * 32 + tn];
                        float br = sWr[(k0 + k) * 32 + tn];
                        #pragma unroll
                        for (int i = 0; i < 8; ++i) {
                            az[i] = fmaf(a[i], bz, az[i]);
                            aq[i] = fmaf(a[i], br, aq[i]);
                        }
                    }
                    if (more) {
                        float* An = Asb + ((((k0 >> 4) & 1) ^ 1)) * (16 * 68);
                        An[(lk4 + 0) * 68 + lm] = nv.x; An[(lk4 + 1) * 68 + lm] = nv.y;
                        An[(lk4 + 2) * 68 + lm] = nv.z; An[(lk4 + 3) * 68 + lm] = nv.w;
                    }
                }
            }
            #pragma unroll
            for (int i = 0; i < 8; ++i) {
                int b = bm0 + tm * 8 + i;
                zg[i] = sigmoidf_(az[i] + lz[i] + bgz);
                float rg = sigmoidf_(aq[i] + lr[i] + bgr);
                g_rh[b * KS + j] = rg * hsv[i];
            }
            grid_barrier();

            float al[8];
            #pragma unroll
            for (int i = 0; i < 8; ++i) al[i] = 0.f;
            {
                float4 av = __ldcg((const float4*)&g_rh[(size_t)(bm0 + lm) * KS + lk4]);
                Asb[(lk4 + 0) * 68 + lm] = av.x; Asb[(lk4 + 1) * 68 + lm] = av.y;
                Asb[(lk4 + 2) * 68 + lm] = av.z; Asb[(lk4 + 3) * 68 + lm] = av.w;
                for (int k0 = 0; k0 < KS; k0 += 16) {
                    __syncthreads();
                    float4 nv;
                    const bool more = (k0 + 16 < KS);
                    if (more)
                        nv = __ldcg((const float4*)&g_rh[(size_t)(bm0 + lm) * KS + k0 + 16 + lk4]);
                    const float* Ac = Asb + ((k0 >> 4) & 1) * (16 * 68);
                    #pragma unroll
                    for (int k = 0; k < 16; ++k) {
                        float a[8];
                        *(float4*)(a)     = *(const float4*)(Ac + k * 68 + tm * 8);
                        *(float4*)(a + 4) = *(const float4*)(Ac + k * 68 + tm * 8 + 4);
                        float bl = sWl[(k0 + k) * 32 + tn];
                        #pragma unroll
                        for (int i = 0; i < 8; ++i)
                            al[i] = fmaf(a[i], bl, al[i]);
                    }
                    if (more) {
                        float* An = Asb + ((((k0 >> 4) & 1) ^ 1)) * (16 * 68);
                        An[(lk4 + 0) * 68 + lm] = nv.x; An[(lk4 + 1) * 68 + lm] = nv.y;
                        An[(lk4 + 2) * 68 + lm] = nv.z; An[(lk4 + 3) * 68 + lm] = nv.w;
                    }
                }
            }
            float* hsw = g_hsbuf[rp ^ 1];
            #pragma unroll
            for (int i = 0; i < 8; ++i) {
                int b = bm0 + tm * 8 + i;
                float kv = zg[i] * (tanhf(ll[i] + al[i] + blv) - hsv[i]);
                if (st == 0) {
                    kacc[i] = kv;
                    hsv[i] = hbv[i] + 0.5f * dtv[i] * kv;
                } else if (st == 1) {
                    kacc[i] += 2.f * kv;
                    hsv[i] = hbv[i] + 0.5f * dtv[i] * kv;
                } else if (st == 2) {
                    kacc[i] += 2.f * kv;
                    hsv[i] = hbv[i] + dtv[i] * kv;
                } else {
                    float hn = hbv[i] + dtv[i] * (kacc[i] + kv) * (1.f / 6.f);
                    hsv[i] = hn;
                    hbv[i] = hn;
                    g_states[((size_t)t * BDIM + b) * KS + j] = hn;
                }
                hsw[b * KS + j] = hsv[i];
            }
            rp ^= 1;
            grid_barrier();
        }
    }
}

// ---------------- y = T @ Ly2^T  -> out rows 1..255 ------------------------
__global__ __launch_bounds__(256)
void y_kernel(const float* __restrict__ Ly2, float* __restrict__ out) {
    __shared__ float sL[KOUT][KS];
    for (int u = threadIdx.x; u < KOUT * KS; u += 256)
        sL[u >> 9][u & 511] = Ly2[u];
    __syncthreads();
    int w = threadIdx.x >> 5, lane = threadIdx.x & 31;
    int row = blockIdx.x * 8 + w;
    const float* tr = g_xe + (size_t)row * KS;
    float acc[KOUT] = {0.f, 0.f, 0.f, 0.f, 0.f, 0.f, 0.f, 0.f};
    #pragma unroll
    for (int c = 0; c < 4; ++c) {
        float4 v = *(const float4*)&tr[c * 128 + lane * 4];
        #pragma unroll
        for (int o = 0; o < KOUT; ++o) {
            float4 lv = *(const float4*)&sL[o][c * 128 + lane * 4];
            acc[o] += v.x * lv.x + v.y * lv.y + v.z * lv.z + v.w * lv.w;
        }
    }
    #pragma unroll
    for (int o = 0; o < KOUT; ++o)
        #pragma unroll
        for (int sh = 16; sh; sh >>= 1)
            acc[o] += __shfl_xor_sync(0xffffffffu, acc[o], sh);
    if (lane == 0) {
        int t = row >> 9, b = row & 511;
        float* op = out + ((size_t)((t + 1) << 9) + b) * KOUT;
        *(float4*)(op)     = make_float4(acc[0], acc[1], acc[2], acc[3]);
        *(float4*)(op + 4) = make_float4(acc[4], acc[5], acc[6], acc[7]);
    }
}

// ------------------------------- launcher ----------------------------------
extern "C" void kernel_launch(void* const* d_in, const int* in_sizes, int n_in,
                              void* d_out, int out_size) {
    const float* seq    = (const float*)d_in[0];
    const float* state0 = (const float*)d_in[1];
    const float* Win    = (const float*)d_in[2];
    const float* bin    = (const float*)d_in[3];
    const float* Wx     = (const float*)d_in[4];
    const float* Wg     = (const float*)d_in[5];
    const float* bg     = (const float*)d_in[6];
    const float* Wlin   = (const float*)d_in[7];
    const float* blin   = (const float*)d_in[8];
    const float* Ly1    = (const float*)d_in[9];
    const float* Ly2    = (const float*)d_in[10];
    float* out = (float*)d_out;

    float *p_xe = nullptr, *p_Lx = nullptr, *p_states = nullptr;
    cudaGetSymbolAddress((void**)&p_xe,     g_xe);
    cudaGetSymbolAddress((void**)&p_Lx,     g_Lx);
    cudaGetSymbolAddress((void**)&p_states, g_states);

    // scan kernel smem: 3*512*32 f32 weights + 2*16*68 f32 A-tiles = 205,312 B
    const int scan_smem = 3 * KS * 32 * 4 + 2 * 16 * 68 * 4;
    cudaFuncSetAttribute(scan_kernel,
                         cudaFuncAttributeMaxDynamicSharedMemorySize, scan_smem);

    // Phase 0: init state buffer + output row 0
    init_kernel<<<(BDIM * KS) / 256, 256>>>(state0);
    y0_kernel<<<1, 512>>>(state0, Ly1, Ly2, out);

    // Phase 1: xe
    xe_kernel<<<LB / 4, 256>>>(seq, Win, bin);

    // Phase 2: Lx = xe @ Wx^T  (131072 x 1536 x 512), 3xTF32 split tensor core
    sgemm_tc<false, true><<<dim3(NWX / 128, LB / 128), 256>>>(p_xe, Wx, p_Lx, LB, NWX, KS);

    // Phase 3: persistent RK4 scan (single launch, 2048 internal barriers)
    scan_kernel<<<NB, 256, scan_smem>>>(seq, Wg, Wlin, bg, blin, state0);

    // Phase 4: output head, 3xTF32 split for ~fp32 accuracy (feeds output)
    const int MT = (LSEQ - 1) * BDIM;   // 130560, divisible by 128
    sgemm_tc<true, true><<<dim3(KS / 128, MT / 128), 256>>>(p_states, Ly1, p_xe, MT, KS, KS);
    y_kernel<<<MT / 8, 256>>>(Ly2, out);
}